// round 11
// baseline (speedup 1.0000x reference)
#include <cuda_runtime.h>
#include <stdint.h>

#define B_SZ 65536
#define NM 5
#define WPB 8
#define SPB (WPB * 2)            // 16 samples per block (2 per warp)
#define NBLOCKS (B_SZ / SPB)     // 4096

__device__ float g_partials[NBLOCKS];
__device__ unsigned g_count;     // zero-init; self-resets every launch

__device__ __forceinline__ float sqrt_ap(float x) {
    float r;
    asm("sqrt.approx.f32 %0, %1;" : "=f"(r) : "f"(x));
    return r;
}

// Smooth-L1 (huber, delta=1): ad<1 ? 0.5 d^2 : ad-0.5 == t*(ad - 0.5t), t=min(ad,1)
__device__ __forceinline__ float huber(float d) {
    float ad = fabsf(d);
    float t = fminf(ad, 1.0f);
    return t * fmaf(-0.5f, t, ad);
}

__device__ __forceinline__ uint32_t rotl32(uint32_t x, uint32_t d) {
    return __funnelshift_l(x, x, d);
}

// JAX partitionable ThreeFry-2x32: key=(0,42), counter=(0,i); randint(0,5) -> (x0^x1) % 5
__device__ __forceinline__ int threefry_mod5(uint32_t i) {
    const uint32_t k0 = 0u, k1 = 42u;
    const uint32_t k2 = k0 ^ k1 ^ 0x1BD11BDAu;
    uint32_t x0 = k0;
    uint32_t x1 = i + k1;
#define TF4(r0, r1, r2, r3)                           \
    x0 += x1; x1 = rotl32(x1, r0); x1 ^= x0;          \
    x0 += x1; x1 = rotl32(x1, r1); x1 ^= x0;          \
    x0 += x1; x1 = rotl32(x1, r2); x1 ^= x0;          \
    x0 += x1; x1 = rotl32(x1, r3); x1 ^= x0;
    TF4(13, 15, 26, 6)   x0 += k1; x1 += k2 + 1u;
    TF4(17, 29, 16, 24)  x0 += k2; x1 += k0 + 2u;
    TF4(13, 15, 26, 6)   x0 += k0; x1 += k1 + 3u;
    TF4(17, 29, 16, 24)  x0 += k1; x1 += k2 + 4u;
    TF4(13, 15, 26, 6)   x0 += k2; x1 += k0 + 5u;
#undef TF4
    return (int)((x0 ^ x1) % 5u);
}

// dist-based argmin over eligible modes (heavy path, ~13% of samples)
// b = tp + 2*lane; off = 0 (sample A) or 505 (sample B)
__device__ __forceinline__ void heavy_best(
    const float* __restrict__ b, int off, float2 g0, float2 g1, bool has2,
    unsigned emask, int& best, float& rs) {
    const unsigned FULL = 0xffffffffu;
    const float INF = __int_as_float(0x7f800000);
    float bestKey = INF;
    best = 0;
#pragma unroll
    for (int m = 0; m < NM; m++) {
        if (emask >> m & 1u) {                 // warp-uniform
            int i = off + m * 100;
            float dx = b[i] - g0.x, dy = b[i + 1] - g0.y;
            float dsum = sqrt_ap(fmaf(dx, dx, dy * dy));
            if (has2) {
                float ex = b[i + 64] - g1.x, ey = b[i + 65] - g1.y;
                dsum += sqrt_ap(fmaf(ex, ex, ey * ey));
            }
#pragma unroll
            for (int o = 16; o; o >>= 1) dsum += __shfl_xor_sync(FULL, dsum, o);
            if (dsum < bestKey) { bestKey = dsum; best = m; }  // strict < = first-min
        }
    }
    int c = off + best * 100;                  // reload true winner (L1/L2-hot)
    rs = huber(b[c] - g0.x) + huber(b[c + 1] - g0.y);
    if (has2) rs += huber(b[c + 64] - g1.x) + huber(b[c + 65] - g1.y);
}

__global__ void __launch_bounds__(32 * WPB, 8)
combo_fused(const float* __restrict__ path_pred,
            const float* __restrict__ path_gt,
            const float* __restrict__ cr_pred,
            const float* __restrict__ cr_gt,
            float* __restrict__ out) {
    __shared__ float warp_sums[WPB];
    __shared__ bool  is_last;
    const unsigned FULL = 0xffffffffu;
    const float INF = __int_as_float(0x7f800000);
    const float COS5 = 0.99619469809174553f;
    int lane = threadIdx.x & 31;
    int w = threadIdx.x >> 5;
    int sA = blockIdx.x * SPB + 2 * w;

    const float* tp = path_pred + (size_t)sA * 505;                  // sample A base; B at +505
    const float2* gt = (const float2*)(path_gt + (size_t)sA * 100);  // A rows; B at +50

    // ---- batch 1: ALL unconditional loads first (before any ALU chains) ----
    bool has2 = (lane < 18);
    float2 g0A = gt[lane],        g0B = gt[50 + lane];
    float2 g1A = make_float2(0.f, 0.f), g1B = make_float2(0.f, 0.f);
    if (has2) { g1A = gt[32 + lane]; g1B = gt[82 + lane]; }

    // eligibility lanes: 0..4 = modes of A, 8..12 = modes of B
    bool isB = (lane >= 8);
    int  mlane = lane & 7;                      // mode index within group
    bool eligLane = (mlane < NM) && (lane < 16);
    float ex = 0.f, ey = 0.f, pr = -INF;
    if (eligLane) {
        int base = (isB ? 505 : 0) + mlane * 100 + 98;
        ex = tp[base]; ey = tp[base + 1];
        pr = tp[(isB ? 1005 : 500) + mlane];    // logits
    }
    float crp = 0.f, cry = 0.f;
    if (lane == 0 || lane == 8) {               // BCE inputs: lane0 = A, lane8 = B
        int si = sA + (lane >> 3);
        crp = cr_pred[si]; cry = cr_gt[si];
    }

    // ---- ThreeFry AFTER load issue: ~150-cycle hash hides under memory latency ----
    int tfv = threefry_mod5((uint32_t)(sA + (lane & 1)));
    int rndA = __shfl_sync(FULL, tfv, 0);
    int rndB = __shfl_sync(FULL, tfv, 1);

    // ---- batch 2: speculative huber loads for the rand modes (both samples) ----
    const float* b = tp + 2 * lane;             // shared base; B via +505 offsets
    int iA = rndA * 100;
    int iB = 505 + rndB * 100;
    float sx0A = b[iA], sy0A = b[iA + 1], sx0B = b[iB], sy0B = b[iB + 1];
    float sx1A = 0.f, sy1A = 0.f, sx1B = 0.f, sy1B = 0.f;
    if (has2) {
        sx1A = b[iA + 64]; sy1A = b[iA + 65];
        sx1B = b[iB + 64]; sy1B = b[iB + 65];
    }

    // ref last points via shfl from lane 17 (g1A/g1B hold gt[49]/gt[99] there)
    float rAx = __shfl_sync(FULL, g1A.x, 17), rAy = __shfl_sync(FULL, g1A.y, 17);
    float rBx = __shfl_sync(FULL, g1B.x, 17), rBy = __shfl_sync(FULL, g1B.y, 17);

    // ---- eligibility, computed once on split lanes ----
    float rfx = isB ? rBx : rAx, rfy = isB ? rBy : rAy;
    float rn = sqrt_ap(fmaf(rfx, rfx, rfy * rfy));
    bool elig = false;
    if (eligLane) {
        float tn = sqrt_ap(fmaf(ex, ex, ey * ey));
        float np = rn * tn;
        float dot = fmaf(rfx, ex, rfy * ey);
        bool nanm = isnan(rfx) || isnan(rfy) || isnan(ex) || isnan(ey);
        elig = nanm ? false : (np == 0.f ? true : (dot >= COS5 * np));
    }
    unsigned em = __ballot_sync(FULL, elig);
    unsigned emA = em & 0x1fu;
    unsigned emB = (em >> 8) & 0x1fu;

    // ---- per-sample best + rsum partial (fast path uses speculative registers) ----
    int bestA, bestB;
    float rsA, rsB;
    if (emA) {
        heavy_best(b, 0, g0A, g1A, has2, emA, bestA, rsA);
    } else {
        bestA = rndA;
        rsA = huber(sx0A - g0A.x) + huber(sy0A - g0A.y);
        if (has2) rsA += huber(sx1A - g1A.x) + huber(sy1A - g1A.y);
    }
    if (emB) {
        heavy_best(b, 505, g0B, g1B, has2, emB, bestB, rsB);
    } else {
        bestB = rndB;
        rsB = huber(sx0B - g0B.x) + huber(sy0B - g0B.y);
        if (has2) rsB += huber(sx1B - g1B.x) + huber(sy1B - g1B.y);
    }

    // interleaved butterflies: A and B latencies overlap
#pragma unroll
    for (int o = 16; o; o >>= 1) {
        rsA += __shfl_xor_sync(FULL, rsA, o);
        rsB += __shfl_xor_sync(FULL, rsB, o);
    }

    // single octet-butterfly log_softmax: octet 0 reduces A logits, octet 1 reduces B
    float mx = pr;
#pragma unroll
    for (int o = 4; o; o >>= 1) mx = fmaxf(mx, __shfl_xor_sync(FULL, mx, o));
    float e = eligLane ? __expf(pr - mx) : 0.f;
#pragma unroll
    for (int o = 4; o; o >>= 1) e += __shfl_xor_sync(FULL, e, o);
    float pbA = __shfl_sync(FULL, pr, bestA);        // lanes 0..4 hold A logits
    float pbB = __shfl_sync(FULL, pr, 8 + bestB);    // lanes 8..12 hold B logits

    // final per-sample scalar on lanes 0 (A) and 8 (B) simultaneously
    float pb = isB ? pbB : pbA;
    float rs = isB ? rsB : rsA;
    float ce = (mx + __logf(e)) - pb;
    float lp  = fmaxf(__logf(crp), -100.0f);
    float l1p = fmaxf(log1pf(-crp), -100.0f);
    float bce = -(cry * lp + (1.0f - cry) * l1p);
    float contrib = ce + rs * 0.01f + bce;           // valid on lanes 0 and 8 only
    float contribB = __shfl_sync(FULL, contrib, 8);

    if (lane == 0) warp_sums[w] = contrib + contribB;
    __syncthreads();
    if (threadIdx.x == 0) {
        float t = 0.f;
#pragma unroll
        for (int i = 0; i < WPB; i++) t += warp_sums[i];
        g_partials[blockIdx.x] = t;
        __threadfence();
        unsigned done = atomicAdd(&g_count, 1u);
        is_last = (done == NBLOCKS - 1);
    }
    __syncthreads();

    if (is_last) {
        // deterministic finalize: 256 threads, 4 float4 each in fixed order, fixed tree
        __shared__ float sm[32];
        const float4* p4 = (const float4*)g_partials;   // 1024 float4, L2-hot
        float t = 0.f;
#pragma unroll
        for (int i = 0; i < 4; i++) {
            float4 a = p4[threadIdx.x + i * 256];
            t += ((a.x + a.y) + (a.z + a.w));
        }
#pragma unroll
        for (int o = 16; o; o >>= 1) t += __shfl_xor_sync(FULL, t, o);
        if (lane == 0) sm[w] = t;
        __syncthreads();
        if (w == 0) {
            float v = (lane < WPB) ? sm[lane] : 0.f;
#pragma unroll
            for (int o = 4; o; o >>= 1) v += __shfl_xor_sync(FULL, v, o);
            if (lane == 0) {
                out[0] = v * (1.0f / (float)B_SZ);
                g_count = 0;                           // reset for next graph replay
            }
        }
    }
}

extern "C" void kernel_launch(void* const* d_in, const int* in_sizes, int n_in,
                              void* d_out, int out_size) {
    const float* path_pred = (const float*)d_in[0];
    const float* path_gt   = (const float*)d_in[1];
    const float* cr_pred   = (const float*)d_in[2];
    const float* cr_gt     = (const float*)d_in[3];
    // d_in[4] = log_vars (unused by the reference's returned value)
    combo_fused<<<NBLOCKS, 32 * WPB>>>(path_pred, path_gt, cr_pred, cr_gt, (float*)d_out);
}